// round 4
// baseline (speedup 1.0000x reference)
#include <cuda_runtime.h>
#include <math.h>

#define VOCAB 32000
#define NTOK  4096

// Scratch: per-row (A = S - x0 - xt, X = xt), zeros for padding rows.
__device__ float2 g_AX[NTOK];

// ---------------------------------------------------------------------------
// Kernel 1: one block per row. Pure fp32. Gathers x[row][0], x[row][t] are
// issued BEFORE the streaming loop so their latency hides under the stream.
// No fp64, no log(), no dependent tail loads.
// ---------------------------------------------------------------------------
__global__ void __launch_bounds__(256) row_kernel(
    const float* __restrict__ x,
    const void*  __restrict__ target_raw)
{
    const int row = blockIdx.x;
    const size_t rowoff = (size_t)row * VOCAB;
    const float4* __restrict__ p = reinterpret_cast<const float4*>(x + rowoff);
    const int nvec = VOCAB / 4;  // 8000

    // dtype probe (int32 vs int64) + target fetch, warp 0 only
    __shared__ long long s_t;
    if (threadIdx.x < 32) {
        const int* t32 = (const int*)target_raw;
        int v = t32[2 * threadIdx.x + 1];
        unsigned any_nz = __ballot_sync(0xFFFFFFFFu, v != 0);
        if (threadIdx.x == 0) {
            s_t = (any_nz == 0) ? ((const long long*)target_raw)[row]
                                : (long long)t32[row];
        }
    }
    __syncthreads();
    const long long t = s_t;
    const bool valid = (t > 0 && t < VOCAB);

    // Early gathers: overlap with the row stream below.
    float xg = 0.0f;
    if (valid && threadIdx.x < 2)
        xg = x[rowoff + (threadIdx.x == 0 ? (size_t)0 : (size_t)t)];

    float s = 0.0f;
    #pragma unroll 4
    for (int i = threadIdx.x; i < nvec; i += 256) {
        float4 v = p[i];
        s += (v.x + v.y) + (v.z + v.w);
    }

    // warp reduce
    #pragma unroll
    for (int o = 16; o > 0; o >>= 1)
        s += __shfl_xor_sync(0xFFFFFFFFu, s, o);

    __shared__ float wsum[8];
    __shared__ float s_xt;
    const int warp = threadIdx.x >> 5;
    if ((threadIdx.x & 31) == 0) wsum[warp] = s;
    if (threadIdx.x == 1) s_xt = xg;
    __syncthreads();

    if (threadIdx.x == 0) {
        float S = 0.0f;
        #pragma unroll
        for (int w = 0; w < 8; w++) S += wsum[w];
        float2 ax = make_float2(0.0f, 0.0f);
        if (valid) {
            ax.x = S - xg - s_xt;   // S - x0 - xt
            ax.y = s_xt;            // xt
        }
        g_AX[row] = ax;
    }
}

// ---------------------------------------------------------------------------
// Kernel 2: single block. total = cnt*K1 - base*sum(A) - conf*sum(X), double.
// K1 (needs log) computed exactly once here.
// ---------------------------------------------------------------------------
__global__ void __launch_bounds__(256) reduce_kernel(
    const void* __restrict__ target_raw,
    float* __restrict__ out)
{
    __shared__ bool s_is64;
    if (threadIdx.x < 32) {
        const int* t32 = (const int*)target_raw;
        int v = t32[2 * threadIdx.x + 1];
        unsigned any_nz = __ballot_sync(0xFFFFFFFFu, v != 0);
        if (threadIdx.x == 0) s_is64 = (any_nz == 0);
    }
    __syncthreads();
    const bool is64 = s_is64;
    const int* __restrict__ t32 = (const int*)target_raw;
    const long long* __restrict__ t64 = (const long long*)target_raw;

    double accA = 0.0, accX = 0.0;
    int cnt = 0;
    for (int r = threadIdx.x; r < NTOK; r += 256) {
        float2 ax = g_AX[r];
        accA += (double)ax.x;
        accX += (double)ax.y;
        const long long t = is64 ? t64[r] : (long long)t32[r];
        cnt += (t > 0 && t < VOCAB) ? 1 : 0;
    }

    #pragma unroll
    for (int o = 16; o > 0; o >>= 1) {
        accA += __shfl_xor_sync(0xFFFFFFFFu, accA, o);
        accX += __shfl_xor_sync(0xFFFFFFFFu, accX, o);
        cnt  += __shfl_xor_sync(0xFFFFFFFFu, cnt,  o);
    }

    __shared__ double wA[8], wX[8];
    __shared__ int wC[8];
    const int warp = threadIdx.x >> 5;
    if ((threadIdx.x & 31) == 0) { wA[warp] = accA; wX[warp] = accX; wC[warp] = cnt; }
    __syncthreads();

    if (threadIdx.x == 0) {
        double A = 0.0, X = 0.0;
        int C = 0;
        #pragma unroll
        for (int w = 0; w < 8; w++) { A += wA[w]; X += wX[w]; C += wC[w]; }

        const double base = 0.1 / 31999.0;   // SMOOTHING / (V-1)
        const double conf = 0.9;             // 1 - SMOOTHING
        const double K1 = (double)(VOCAB - 2) * base * log(base)
                        + conf * log(conf);

        out[0] = (float)((double)C * K1 - base * A - conf * X);
    }
}

extern "C" void kernel_launch(void* const* d_in, const int* in_sizes, int n_in,
                              void* d_out, int out_size) {
    const float* model_output = (const float*)d_in[0];
    const void*  target       = (const void*)d_in[1];
    float* out = (float*)d_out;

    row_kernel<<<NTOK, 256>>>(model_output, target);
    reduce_kernel<<<1, 256>>>(target, out);
}

// round 6
// speedup vs baseline: 1.1891x; 1.1891x over previous
#include <cuda_runtime.h>
#include <math.h>

#define VOCAB 32000
#define NTOK  4096

// Deterministic fixed-point accumulator (2^42 scale) + completion counter.
__device__ long long g_sum   = 0;
__device__ unsigned  g_count = 0;

// ---------------------------------------------------------------------------
// Single fused kernel: one block per row.
//  - streams the 128KB row with float4 loads (DRAM-bound part)
//  - warp 0 speculatively loads target under BOTH dtype interpretations at the
//    head and issues both clamped gathers mid-stream (fully overlapped)
//  - dtype resolved by a tail ballot over the first 32 odd int32 words
//  - row loss accumulated via integer atomicAdd (order-independent => exact,
//    deterministic); last block converts, writes out[0], resets state.
// ---------------------------------------------------------------------------
__global__ void __launch_bounds__(256) fused_kernel(
    const float* __restrict__ x,
    const void*  __restrict__ target_raw,
    float* __restrict__ out)
{
    const int row = blockIdx.x;
    const size_t rowoff = (size_t)row * VOCAB;
    const float4* __restrict__ p = reinterpret_cast<const float4*>(x + rowoff);

    const int tid  = threadIdx.x;
    const int lane = tid & 31;
    const int warp = tid >> 5;

    const int* __restrict__ t32 = (const int*)target_raw;

    // Head: independent loads (probe word per lane; both target interpretations)
    int pv = 0, tw_a = 0, lo = 0, hi = 0;
    if (warp == 0) {
        pv = t32[2 * lane + 1];           // odd words: int64 high words OR int32 targets
        if (lane == 0) {
            tw_a = t32[row];              // int32 interpretation
            lo   = t32[2 * row];          // int64 low word
            hi   = t32[2 * row + 1];      // int64 high word
        }
    }

    // ---- stream, part 1 (covers the latency of the target-word loads) ----
    float s = 0.0f;
    #pragma unroll 4
    for (int i = tid; i < 2048; i += 256) {
        float4 v = p[i];
        s += (v.x + v.y) + (v.z + v.w);
    }

    // Mid-stream: issue speculative gathers (both interpretations, clamped safe)
    float x0 = 0.0f, xa = 0.0f, xb = 0.0f;
    if (warp == 0 && lane == 0) {
        int ca = (tw_a > 0 && tw_a < VOCAB) ? tw_a : 0;
        int cb = (hi == 0 && lo > 0 && lo < VOCAB) ? lo : 0;
        x0 = x[rowoff];
        xa = x[rowoff + (size_t)ca];
        xb = x[rowoff + (size_t)cb];
    }

    // ---- stream, part 2 (covers gather latency) ----
    #pragma unroll 4
    for (int i = 2048 + tid; i < 8000; i += 256) {
        float4 v = p[i];
        s += (v.x + v.y) + (v.z + v.w);
    }

    // warp reduce
    #pragma unroll
    for (int o = 16; o > 0; o >>= 1)
        s += __shfl_xor_sync(0xFFFFFFFFu, s, o);

    __shared__ float wsum[8];
    if (lane == 0) wsum[warp] = s;

    // Tail: resolve dtype (all 32 odd words zero <=> int64)
    bool  valid = false;
    float xt = 0.0f;
    if (warp == 0) {
        unsigned nz = __ballot_sync(0xFFFFFFFFu, pv != 0);
        if (lane == 0) {
            const bool is64 = (nz == 0);
            const long long t = is64 ? ((hi == 0) ? (long long)lo : -1LL)
                                     : (long long)tw_a;
            valid = (t > 0 && t < VOCAB);
            xt = is64 ? xb : xa;
        }
    }
    __syncthreads();

    if (tid == 0) {
        float S = 0.0f;
        #pragma unroll
        for (int w = 0; w < 8; w++) S += wsum[w];

        double loss = 0.0;
        if (valid) {
            const double base    = 0.1 / 31999.0;            // SMOOTHING/(V-1)
            const double LN_BASE = -12.676045024287623;      // ln(0.1/31999)
            const double LN_CONF = -0.10536051565782628;     // ln(0.9)
            // K1 = (V-2)*base*ln(base) + conf*ln(conf)   -- V-2 = 31998 (!)
            const double K1 = (double)(VOCAB - 2) * base * LN_BASE
                            + 0.9 * LN_CONF;
            loss = K1 - base * ((double)S - (double)x0 - (double)xt)
                      - 0.9 * (double)xt;
        }
        const long long ll = llrint(loss * 4398046511104.0); // * 2^42
        atomicAdd((unsigned long long*)&g_sum, (unsigned long long)ll);
        __threadfence();
        const unsigned prev = atomicAdd(&g_count, 1u);
        if (prev == (unsigned)(gridDim.x - 1)) {
            const long long tot = *(volatile long long*)&g_sum;
            out[0] = (float)((double)tot * (1.0 / 4398046511104.0));
            g_sum = 0;          // reset for next graph replay
            g_count = 0;
        }
    }
}

extern "C" void kernel_launch(void* const* d_in, const int* in_sizes, int n_in,
                              void* d_out, int out_size) {
    const float* model_output = (const float*)d_in[0];
    const void*  target       = (const void*)d_in[1];
    float* out = (float*)d_out;

    fused_kernel<<<NTOK, 256>>>(model_output, target, out);
}